// round 4
// baseline (speedup 1.0000x reference)
#include <cuda_runtime.h>
#include <cstdint>

// ---------------- Problem constants ----------------
#define NB      64          // batch
#define NPG     180         // nodes per graph
#define NN      (NB*NPG)    // 11520 nodes
#define NE      (NN*16)     // 184320 edges (random part; self loops handled implicitly)
#define NH      4           // heads
#define FC      256         // channels per head
#define HF      1024        // NH*FC
#define LAT     256
#define BOT     128
#define KIN     (LAT+BOT)   // 384
#define NEG_SLOPE 0.2f
#define MAXE    1024        // per-dst edge cap for smem (max observed degree ~45)

// ---------------- Scratch (device globals; no allocation allowed) ----------------
__device__ float g_xin[NB*KIN];
__device__ float g_zc [NB*LAT];          // relu(zc) [64,256]
__device__ float g_Y  [NB*HF];           // relu(zc) @ W1[:256,:]  [64,1024]
__device__ float g_h  [(size_t)NN*HF];   // current h = xW
__device__ float g_x  [(size_t)NN*HF];   // aggregated + bias + relu
__device__ float g_as [NN*NH];
__device__ float g_ad [NN*NH];
__device__ float g_t  [(size_t)NN*FC];   // head intermediate
__device__ int   g_cnt[NN];
__device__ int   g_rowptr[NN+1];
__device__ int   g_wp [NN];
__device__ int   g_col[NE];

// ---------------- small utility kernels ----------------
__global__ void concat_k(const float* __restrict__ z, const float* __restrict__ c,
                         float* __restrict__ out)
{
    int idx = blockIdx.x*blockDim.x + threadIdx.x;
    if (idx >= NB*KIN) return;
    int b = idx / KIN, i = idx % KIN;
    out[idx] = (i < LAT) ? z[b*LAT + i] : c[b*BOT + (i-LAT)];
}

__global__ void build_h1_k(const float* __restrict__ Y, const float* __restrict__ W1,
                           float* __restrict__ h)
{
    int idx = blockIdx.x*blockDim.x + threadIdx.x;   // over NN*256 float4s
    if (idx >= NN*(HF/4)) return;
    int n  = idx >> 8;
    int c4 = (idx & 255) << 2;
    int b = n / NPG, o = n % NPG;
    float4 yv = *(const float4*)(Y + (size_t)b*HF + c4);
    float4 wv = *(const float4*)(W1 + (size_t)(LAT + o)*HF + c4);
    yv.x += wv.x; yv.y += wv.y; yv.z += wv.z; yv.w += wv.w;
    *(float4*)(h + (size_t)n*HF + c4) = yv;
}

__global__ void zero_cnt_k(int* __restrict__ cnt)
{
    int i = blockIdx.x*blockDim.x + threadIdx.x;
    if (i < NN) cnt[i] = 0;
}

__global__ void count_k(const int* __restrict__ dst, int* __restrict__ cnt)
{
    int e = blockIdx.x*blockDim.x + threadIdx.x;
    if (e < NE) atomicAdd(&cnt[dst[e]], 1);
}

__global__ void scan_k(const int* __restrict__ cnt, int* __restrict__ rowptr,
                       int* __restrict__ wp)
{
    __shared__ int sums[256];
    const int CH = (NN + 255) / 256;     // 45
    int t = threadIdx.x;
    int base = t * CH;
    int s = 0;
    for (int i = 0; i < CH; i++) {
        int idx = base + i;
        if (idx < NN) s += cnt[idx];
    }
    sums[t] = s;
    __syncthreads();
    if (t == 0) {
        int run = 0;
        for (int i = 0; i < 256; i++) { int v = sums[i]; sums[i] = run; run += v; }
        rowptr[NN] = run;
    }
    __syncthreads();
    int run = sums[t];
    for (int i = 0; i < CH; i++) {
        int idx = base + i;
        if (idx < NN) { rowptr[idx] = run; wp[idx] = run; run += cnt[idx]; }
    }
}

__global__ void scatter_k(const int* __restrict__ src, const int* __restrict__ dst,
                          int* __restrict__ wp, int* __restrict__ col)
{
    int e = blockIdx.x*blockDim.x + threadIdx.x;
    if (e >= NE) return;
    int d = dst[e];
    int p = atomicAdd(&wp[d], 1);
    col[p] = src[e];
}

// ---------------- attention coefficients ----------------
__global__ void att_k(const float* __restrict__ h,
                      const float* __restrict__ att_s, const float* __restrict__ att_d,
                      float* __restrict__ as_, float* __restrict__ ad_)
{
    int gw   = (blockIdx.x*blockDim.x + threadIdx.x) >> 5;
    int lane = threadIdx.x & 31;
    if (gw >= NN*NH) return;
    int n = gw >> 2, hh = gw & 3;
    const float* hp = h + (size_t)n*HF + hh*FC;
    const float* sp = att_s + hh*FC;
    const float* dp = att_d + hh*FC;
    float s = 0.f, d = 0.f;
    #pragma unroll 4
    for (int c = lane; c < FC; c += 32) {
        float v = hp[c];
        s += v * sp[c];
        d += v * dp[c];
    }
    #pragma unroll
    for (int o = 16; o; o >>= 1) {
        s += __shfl_down_sync(0xffffffffu, s, o);
        d += __shfl_down_sync(0xffffffffu, d, o);
    }
    if (lane == 0) { as_[n*NH+hh] = s; ad_[n*NH+hh] = d; }
}

// ---------------- per-dst softmax + aggregation (+bias+relu) ----------------
__global__ void agg_k(const float* __restrict__ h,
                      const float* __restrict__ as_, const float* __restrict__ ad_,
                      const int* __restrict__ rowptr, const int* __restrict__ col,
                      const float* __restrict__ bias, float* __restrict__ xout)
{
    __shared__ int   src_s[MAXE];
    __shared__ float e_s[MAXE*NH];
    __shared__ float stat[12];     // m[4], inv[4], alpha_self[4]
    __shared__ float ad_sh[4];

    int d   = blockIdx.x;
    int tid = threadIdx.x;
    int r0  = rowptr[d];
    int deg = rowptr[d+1] - r0;
    if (deg > MAXE) deg = MAXE;    // never triggered for this input (max deg ~45)

    if (tid < 4) ad_sh[tid] = ad_[d*NH + tid];
    __syncthreads();

    for (int j = tid; j < deg; j += 256) {
        int s = col[r0 + j];
        src_s[j] = s;
        #pragma unroll
        for (int hh = 0; hh < NH; hh++) {
            float e = as_[s*NH + hh] + ad_sh[hh];
            e = (e > 0.f) ? e : NEG_SLOPE * e;
            e_s[j*NH + hh] = e;
        }
    }
    __syncthreads();

    if (tid < 4) {
        int hh = tid;
        float eself = as_[d*NH + hh] + ad_sh[hh];
        eself = (eself > 0.f) ? eself : NEG_SLOPE * eself;
        float m = eself;
        for (int j = 0; j < deg; j++) m = fmaxf(m, e_s[j*NH + hh]);
        float s = __expf(eself - m);
        for (int j = 0; j < deg; j++) s += __expf(e_s[j*NH + hh] - m);
        float inv = 1.f / (s + 1e-16f);
        stat[hh]     = m;
        stat[4 + hh] = inv;
        stat[8 + hh] = __expf(eself - m) * inv;
    }
    __syncthreads();

    for (int j = tid; j < deg; j += 256) {
        #pragma unroll
        for (int hh = 0; hh < NH; hh++)
            e_s[j*NH + hh] = __expf(e_s[j*NH + hh] - stat[hh]) * stat[4 + hh];
    }
    __syncthreads();

    int c4 = tid * 4;              // channel group (1024 chans / 256 threads)
    int hh = c4 >> 8;              // head for this channel group
    float4 acc;
    {
        float4 v = *(const float4*)(h + (size_t)d*HF + c4);
        float a = stat[8 + hh];
        acc.x = a*v.x; acc.y = a*v.y; acc.z = a*v.z; acc.w = a*v.w;
    }
    #pragma unroll 4
    for (int j = 0; j < deg; j++) {
        float a = e_s[j*NH + hh];
        float4 v = *(const float4*)(h + (size_t)src_s[j]*HF + c4);
        acc.x += a*v.x; acc.y += a*v.y; acc.z += a*v.z; acc.w += a*v.w;
    }
    float4 bv = *(const float4*)(bias + c4);
    acc.x = fmaxf(acc.x + bv.x, 0.f);
    acc.y = fmaxf(acc.y + bv.y, 0.f);
    acc.z = fmaxf(acc.z + bv.z, 0.f);
    acc.w = fmaxf(acc.w + bv.w, 0.f);
    *(float4*)(xout + (size_t)d*HF + c4) = acc;
}

// ---------------- fp32 tiled GEMM: C[M,Nc] = A[M,K] @ B[K,Nc] (+bias)(+relu) ----------------
// 128x128 tile, BK=8, 256 threads, 8x8 microtile. Nc, K multiples of 8/128 as used.
__global__ void sgemm_k(const float* __restrict__ A, const float* __restrict__ B,
                        const float* __restrict__ bias, float* __restrict__ C,
                        int M, int Nc, int K, int doRelu)
{
    __shared__ float As[8][128];
    __shared__ float Bs[8][128];
    const int tid = threadIdx.x;
    const int bx = blockIdx.x, by = blockIdx.y;

    const int a_row = tid >> 1;
    const int a_k   = (tid & 1) << 2;
    const int b_k   = tid >> 5;
    const int b_col = (tid & 31) << 2;

    const int ty = tid >> 4;
    const int tx = tid & 15;
    const int row0 = by*128 + ty*8;
    const int col0 = bx*128 + tx*8;

    float acc[8][8];
    #pragma unroll
    for (int i = 0; i < 8; i++)
        #pragma unroll
        for (int j = 0; j < 8; j++) acc[i][j] = 0.f;

    const int arow_g = by*128 + a_row;
    for (int k0 = 0; k0 < K; k0 += 8) {
        float4 av = make_float4(0.f,0.f,0.f,0.f);
        if (arow_g < M)
            av = *(const float4*)(A + (size_t)arow_g*K + k0 + a_k);
        As[a_k+0][a_row] = av.x;
        As[a_k+1][a_row] = av.y;
        As[a_k+2][a_row] = av.z;
        As[a_k+3][a_row] = av.w;
        float4 bv = *(const float4*)(B + (size_t)(k0 + b_k)*Nc + bx*128 + b_col);
        *(float4*)&Bs[b_k][b_col] = bv;
        __syncthreads();

        #pragma unroll
        for (int k = 0; k < 8; k++) {
            float ar[8], br[8];
            *(float4*)&ar[0] = *(const float4*)&As[k][ty*8];
            *(float4*)&ar[4] = *(const float4*)&As[k][ty*8+4];
            *(float4*)&br[0] = *(const float4*)&Bs[k][tx*8];
            *(float4*)&br[4] = *(const float4*)&Bs[k][tx*8+4];
            #pragma unroll
            for (int i = 0; i < 8; i++)
                #pragma unroll
                for (int j = 0; j < 8; j++)
                    acc[i][j] += ar[i] * br[j];
        }
        __syncthreads();
    }

    #pragma unroll
    for (int i = 0; i < 8; i++) {
        int r = row0 + i;
        if (r >= M) break;
        #pragma unroll
        for (int j = 0; j < 8; j += 4) {
            float4 v = make_float4(acc[i][j], acc[i][j+1], acc[i][j+2], acc[i][j+3]);
            if (bias) {
                v.x += bias[col0+j+0]; v.y += bias[col0+j+1];
                v.z += bias[col0+j+2]; v.w += bias[col0+j+3];
            }
            if (doRelu) {
                v.x = fmaxf(v.x, 0.f); v.y = fmaxf(v.y, 0.f);
                v.z = fmaxf(v.z, 0.f); v.w = fmaxf(v.w, 0.f);
            }
            *(float4*)(C + (size_t)r*Nc + col0 + j) = v;
        }
    }
}

// ---------------- tiny head projection: out[N,od] = t[N,256] @ Wf[256,od] + bf ----------------
__global__ void head2_k(const float* __restrict__ t, const float* __restrict__ Wf,
                        const float* __restrict__ bf, float* __restrict__ out, int od)
{
    int warp = (blockIdx.x*blockDim.x + threadIdx.x) >> 5;
    int lane = threadIdx.x & 31;
    if (warp >= NN) return;
    const float* tp = t + (size_t)warp*FC;
    float a0 = 0.f, a1 = 0.f;
    #pragma unroll 4
    for (int c = lane; c < FC; c += 32) {
        float v = tp[c];
        a0 += v * Wf[c*od + 0];
        if (od > 1) a1 += v * Wf[c*od + 1];
    }
    #pragma unroll
    for (int o = 16; o; o >>= 1) {
        a0 += __shfl_down_sync(0xffffffffu, a0, o);
        a1 += __shfl_down_sync(0xffffffffu, a1, o);
    }
    if (lane == 0) {
        out[(size_t)warp*od + 0] = a0 + bf[0];
        if (od > 1) out[(size_t)warp*od + 1] = a1 + bf[1];
    }
}

// ---------------- launch ----------------
extern "C" void kernel_launch(void* const* d_in, const int* in_sizes, int n_in,
                              void* d_out, int out_size)
{
    const float* z      = (const float*)d_in[0];
    const float* cond   = (const float*)d_in[1];
    const int*   ei     = (const int*)  d_in[2];   // [2,NE]: src then dst
    const float* W_init = (const float*)d_in[4];
    const float* b_init = (const float*)d_in[5];
    const float* W1  = (const float*)d_in[6];
    const float* as1 = (const float*)d_in[7];
    const float* ad1 = (const float*)d_in[8];
    const float* b1  = (const float*)d_in[9];
    const float* W2  = (const float*)d_in[10];
    const float* as2 = (const float*)d_in[11];
    const float* ad2 = (const float*)d_in[12];
    const float* b2  = (const float*)d_in[13];
    const float* W3  = (const float*)d_in[14];
    const float* as3 = (const float*)d_in[15];
    const float* ad3 = (const float*)d_in[16];
    const float* b3  = (const float*)d_in[17];
    const float* Wp  = (const float*)d_in[18];
    const float* bp  = (const float*)d_in[19];
    const float* Wfp = (const float*)d_in[20];
    const float* bfp = (const float*)d_in[21];
    const float* Ws  = (const float*)d_in[22];
    const float* bs  = (const float*)d_in[23];
    const float* Wfs = (const float*)d_in[24];
    const float* bfs = (const float*)d_in[25];
    const float* Wt  = (const float*)d_in[26];
    const float* bt  = (const float*)d_in[27];
    const float* Wft = (const float*)d_in[28];
    const float* bft = (const float*)d_in[29];
    float* out = (float*)d_out;

    const int* esrc = ei;
    const int* edst = ei + NE;

    float *pxin, *pzc, *pY, *ph, *px, *pas, *pad, *pt;
    int *pcnt, *prow, *pwp, *pcol;
    cudaGetSymbolAddress((void**)&pxin, g_xin);
    cudaGetSymbolAddress((void**)&pzc,  g_zc);
    cudaGetSymbolAddress((void**)&pY,   g_Y);
    cudaGetSymbolAddress((void**)&ph,   g_h);
    cudaGetSymbolAddress((void**)&px,   g_x);
    cudaGetSymbolAddress((void**)&pas,  g_as);
    cudaGetSymbolAddress((void**)&pad,  g_ad);
    cudaGetSymbolAddress((void**)&pt,   g_t);
    cudaGetSymbolAddress((void**)&pcnt, g_cnt);
    cudaGetSymbolAddress((void**)&prow, g_rowptr);
    cudaGetSymbolAddress((void**)&pwp,  g_wp);
    cudaGetSymbolAddress((void**)&pcol, g_col);

    // 1) input projection: relu(concat(z,cond) @ W_init + b_init)  [64,256]
    concat_k<<<(NB*KIN + 255)/256, 256>>>(z, cond, pxin);
    {
        dim3 g(LAT/128, (NB + 127)/128);
        sgemm_k<<<g, 256>>>(pxin, W_init, b_init, pzc, NB, LAT, KIN, 1);
    }
    // 2) Y = relu(zc) @ W1[:256,:]   [64,1024]
    {
        dim3 g(HF/128, (NB + 127)/128);
        sgemm_k<<<g, 256>>>(pzc, W1, nullptr, pY, NB, HF, LAT, 0);
    }
    // 3) CSR by destination (shared by all 3 layers)
    zero_cnt_k<<<(NN + 255)/256, 256>>>(pcnt);
    count_k<<<(NE + 255)/256, 256>>>(edst, pcnt);
    scan_k<<<1, 256>>>(pcnt, prow, pwp);
    scatter_k<<<(NE + 255)/256, 256>>>(esrc, edst, pwp, pcol);

    // 4) h1 = Y[batch] + W1[256+order]  (one-hot trick)
    build_h1_k<<<(NN*(HF/4) + 255)/256, 256>>>(pY, W1, ph);

    // 5) three GAT layers
    const float* ATTS[3] = {as1, as2, as3};
    const float* ATTD[3] = {ad1, ad2, ad3};
    const float* BIAS[3] = {b1, b2, b3};
    const float* WNEXT[2] = {W2, W3};
    for (int L = 0; L < 3; L++) {
        att_k<<<(NN*NH*32 + 255)/256, 256>>>(ph, ATTS[L], ATTD[L], pas, pad);
        agg_k<<<NN, 256>>>(ph, pas, pad, prow, pcol, BIAS[L], px);
        if (L < 2) {
            dim3 g(HF/128, (NN + 127)/128);
            sgemm_k<<<g, 256>>>(px, WNEXT[L], nullptr, ph, NN, HF, HF, 0);
        }
    }

    // 6) heads: t = relu(x @ Wh + bh); out = t @ Wf + bf
    {
        dim3 g(FC/128, (NN + 127)/128);
        sgemm_k<<<g, 256>>>(px, Wp, bp, pt, NN, FC, HF, 1);
        head2_k<<<(NN*32 + 255)/256, 256>>>(pt, Wfp, bfp, out, 2);

        sgemm_k<<<g, 256>>>(px, Ws, bs, pt, NN, FC, HF, 1);
        head2_k<<<(NN*32 + 255)/256, 256>>>(pt, Wfs, bfs, out + (size_t)2*NN, 2);

        sgemm_k<<<g, 256>>>(px, Wt, bt, pt, NN, FC, HF, 1);
        head2_k<<<(NN*32 + 255)/256, 256>>>(pt, Wft, bft, out + (size_t)4*NN, 1);
    }
}

// round 9
// speedup vs baseline: 1.6560x; 1.6560x over previous
#include <cuda_runtime.h>
#include <cstdint>

// ---------------- Problem constants ----------------
#define NB      64
#define NPG     180
#define NN      (NB*NPG)    // 11520
#define NE      (NN*16)     // 184320
#define NH      4
#define FC      256
#define HF      1024
#define LAT     256
#define BOT     128
#define KIN     (LAT+BOT)
#define NEG_SLOPE 0.2f
#define MAXE    96          // per-dst edge cap (Poisson(16): max deg ~38)
#define KC      32          // K chunks of 32 (K = 1024 for all mma GEMMs)

// ---------------- Scratch ----------------
__device__ float g_xin[NB*KIN];
__device__ float g_zc [NB*LAT];
__device__ float g_Y  [NB*HF];
__device__ float g_h  [(size_t)NN*HF];
__device__ float g_x  [(size_t)NN*HF];
__device__ float g_as [NN*NH];
__device__ float g_ad [NN*NH];
__device__ float g_t  [(size_t)NN*FC];
__device__ int   g_cnt[NN];
__device__ int   g_rowptr[NN+1];
__device__ int   g_wp [NN];
__device__ int   g_col[NE];

// ---------------- 3xTF32 mma.sync GEMM ----------------
// C[M,Nc] = A[M,1024] @ B[1024,Nc] (+bias)(+relu).  M % 128 == 0, Nc % 128 == 0.
// CTA tile 128x128, BK=32, 256 threads = 8 warps (4M x 2N), warp tile 32x64.
// Each operand split hi/lo (tf32); acc += hi*hi + hi*lo + lo*hi  -> ~fp32 precision.
#define PA 36
#define PB 132
#define ASTG (128*PA)
#define BSTG (32*PB)
#define STG  (ASTG + BSTG)
#define SMEM_MG (2*STG*4)     // 70656 B

__device__ __forceinline__ void cpa16(uint32_t dst, const float* src) {
    asm volatile("cp.async.cg.shared.global [%0], [%1], 16;" :: "r"(dst), "l"(src));
}
__device__ __forceinline__ uint32_t tf32_hi(float x) {
    uint32_t r;
    asm("cvt.rna.tf32.f32 %0, %1;" : "=r"(r) : "f"(x));
    return r;
}
#define MMA_TF32(ac, a0, a1, a2, a3, b0, b1)                                   \
    asm volatile("mma.sync.aligned.m16n8k8.row.col.f32.tf32.tf32.f32 "         \
        "{%0,%1,%2,%3}, {%4,%5,%6,%7}, {%8,%9}, {%0,%1,%2,%3};"                \
        : "+f"((ac)[0]), "+f"((ac)[1]), "+f"((ac)[2]), "+f"((ac)[3])           \
        : "r"(a0), "r"(a1), "r"(a2), "r"(a3), "r"(b0), "r"(b1))

__global__ void __launch_bounds__(256, 2) mgemm_k(
    const float* __restrict__ A, const float* __restrict__ B, float* __restrict__ C,
    int Nc, const float* __restrict__ bias, int doRelu)
{
    extern __shared__ float sm[];
    const int tid  = threadIdx.x;
    const int wid  = tid >> 5, lane = tid & 31;
    const int wm   = wid >> 1, wn   = wid & 1;
    const int g    = lane >> 2, tig = lane & 3;
    const int m0   = blockIdx.y * 128;
    const int n0   = blockIdx.x * 128;

    float acc[2][8][4];
    #pragma unroll
    for (int mt = 0; mt < 2; mt++)
        #pragma unroll
        for (int nt = 0; nt < 8; nt++)
            #pragma unroll
            for (int i = 0; i < 4; i++) acc[mt][nt][i] = 0.f;

    auto loadst = [&](int c, int s) {
        float* Asm = sm + s*STG;
        float* Bsm = Asm + ASTG;
        const int k0 = c << 5;
        #pragma unroll
        for (int j = 0; j < 4; j++) {
            int idx = tid + j*256;
            int row = idx >> 3, cf = (idx & 7) << 2;
            uint32_t dst = (uint32_t)__cvta_generic_to_shared(Asm + row*PA + cf);
            cpa16(dst, A + (size_t)(m0 + row)*HF + k0 + cf);
        }
        #pragma unroll
        for (int j = 0; j < 4; j++) {
            int idx = tid + j*256;
            int row = idx >> 5, cf = (idx & 31) << 2;
            uint32_t dst = (uint32_t)__cvta_generic_to_shared(Bsm + row*PB + cf);
            cpa16(dst, B + (size_t)(k0 + row)*Nc + n0 + cf);
        }
        asm volatile("cp.async.commit_group;" ::: "memory");
    };

    auto compute = [&](int s) {
        const float* Asm = sm + s*STG;
        const float* Bsm = Asm + ASTG;
        const float* ab = Asm + (wm*32 + g)*PA + tig;
        const float* bb = Bsm + tig*PB + wn*64 + g;
        #pragma unroll
        for (int ks = 0; ks < 4; ks++) {
            uint32_t ah[2][4], al[2][4];
            #pragma unroll
            for (int mt = 0; mt < 2; mt++) {
                const float* p = ab + mt*16*PA + ks*8;
                float f0 = p[0], f1 = p[8*PA], f2 = p[4], f3 = p[8*PA + 4];
                ah[mt][0] = tf32_hi(f0); al[mt][0] = __float_as_uint(f0 - __uint_as_float(ah[mt][0]));
                ah[mt][1] = tf32_hi(f1); al[mt][1] = __float_as_uint(f1 - __uint_as_float(ah[mt][1]));
                ah[mt][2] = tf32_hi(f2); al[mt][2] = __float_as_uint(f2 - __uint_as_float(ah[mt][2]));
                ah[mt][3] = tf32_hi(f3); al[mt][3] = __float_as_uint(f3 - __uint_as_float(ah[mt][3]));
            }
            #pragma unroll
            for (int ntg = 0; ntg < 2; ntg++) {
                uint32_t bh[4][2], bl[4][2];
                #pragma unroll
                for (int q = 0; q < 4; q++) {
                    const float* p = bb + ks*8*PB + (ntg*4 + q)*8;
                    float f0 = p[0], f1 = p[4*PB];
                    bh[q][0] = tf32_hi(f0); bl[q][0] = __float_as_uint(f0 - __uint_as_float(bh[q][0]));
                    bh[q][1] = tf32_hi(f1); bl[q][1] = __float_as_uint(f1 - __uint_as_float(bh[q][1]));
                }
                #pragma unroll
                for (int mt = 0; mt < 2; mt++)
                    #pragma unroll
                    for (int q = 0; q < 4; q++) {
                        float* ac = acc[mt][ntg*4 + q];
                        MMA_TF32(ac, ah[mt][0], ah[mt][1], ah[mt][2], ah[mt][3], bh[q][0], bh[q][1]);
                        MMA_TF32(ac, ah[mt][0], ah[mt][1], ah[mt][2], ah[mt][3], bl[q][0], bl[q][1]);
                        MMA_TF32(ac, al[mt][0], al[mt][1], al[mt][2], al[mt][3], bh[q][0], bh[q][1]);
                    }
            }
        }
    };

    loadst(0, 0);
    loadst(1, 1);
    for (int c = 0; c < KC; c++) {
        int s = c & 1;
        if (c < KC - 2) asm volatile("cp.async.wait_group 1;" ::: "memory");
        else            asm volatile("cp.async.wait_group 0;" ::: "memory");
        __syncthreads();
        compute(s);
        __syncthreads();
        if (c + 2 < KC) loadst(c + 2, s);
    }

    // epilogue
    #pragma unroll
    for (int mt = 0; mt < 2; mt++) {
        int r = m0 + wm*32 + mt*16 + g;
        #pragma unroll
        for (int nt = 0; nt < 8; nt++) {
            int col = n0 + wn*64 + nt*8 + 2*tig;
            float2 v0 = make_float2(acc[mt][nt][0], acc[mt][nt][1]);
            float2 v1 = make_float2(acc[mt][nt][2], acc[mt][nt][3]);
            if (bias) {
                float2 bv = *(const float2*)(bias + col);
                v0.x += bv.x; v0.y += bv.y;
                v1.x += bv.x; v1.y += bv.y;
            }
            if (doRelu) {
                v0.x = fmaxf(v0.x, 0.f); v0.y = fmaxf(v0.y, 0.f);
                v1.x = fmaxf(v1.x, 0.f); v1.y = fmaxf(v1.y, 0.f);
            }
            *(float2*)(C + (size_t)r*Nc + col)       = v0;
            *(float2*)(C + (size_t)(r + 8)*Nc + col) = v1;
        }
    }
}

// ---------------- small utility kernels ----------------
__global__ void concat_k(const float* __restrict__ z, const float* __restrict__ c,
                         float* __restrict__ out)
{
    int idx = blockIdx.x*blockDim.x + threadIdx.x;
    if (idx >= NB*KIN) return;
    int b = idx / KIN, i = idx % KIN;
    out[idx] = (i < LAT) ? z[b*LAT + i] : c[b*BOT + (i-LAT)];
}

__global__ void build_h1_k(const float* __restrict__ Y, const float* __restrict__ W1,
                           float* __restrict__ h)
{
    int idx = blockIdx.x*blockDim.x + threadIdx.x;
    if (idx >= NN*(HF/4)) return;
    int n  = idx >> 8;
    int c4 = (idx & 255) << 2;
    int b = n / NPG, o = n % NPG;
    float4 yv = *(const float4*)(Y + (size_t)b*HF + c4);
    float4 wv = *(const float4*)(W1 + (size_t)(LAT + o)*HF + c4);
    yv.x += wv.x; yv.y += wv.y; yv.z += wv.z; yv.w += wv.w;
    *(float4*)(h + (size_t)n*HF + c4) = yv;
}

__global__ void zero_cnt_k(int* __restrict__ cnt)
{
    int i = blockIdx.x*blockDim.x + threadIdx.x;
    if (i < NN) cnt[i] = 0;
}

__global__ void count_k(const int* __restrict__ dst, int* __restrict__ cnt)
{
    int e = blockIdx.x*blockDim.x + threadIdx.x;
    if (e < NE) atomicAdd(&cnt[dst[e]], 1);
}

__global__ void scan_k(const int* __restrict__ cnt, int* __restrict__ rowptr,
                       int* __restrict__ wp)
{
    __shared__ int sums[256];
    const int CH = (NN + 255) / 256;
    int t = threadIdx.x;
    int base = t * CH;
    int s = 0;
    for (int i = 0; i < CH; i++) { int idx = base + i; if (idx < NN) s += cnt[idx]; }
    sums[t] = s;
    __syncthreads();
    if (t == 0) {
        int run = 0;
        for (int i = 0; i < 256; i++) { int v = sums[i]; sums[i] = run; run += v; }
        rowptr[NN] = run;
    }
    __syncthreads();
    int run = sums[t];
    for (int i = 0; i < CH; i++) {
        int idx = base + i;
        if (idx < NN) { rowptr[idx] = run; wp[idx] = run; run += cnt[idx]; }
    }
}

__global__ void scatter_k(const int* __restrict__ src, const int* __restrict__ dst,
                          int* __restrict__ wp, int* __restrict__ col)
{
    int e = blockIdx.x*blockDim.x + threadIdx.x;
    if (e >= NE) return;
    int d = dst[e];
    int p = atomicAdd(&wp[d], 1);
    col[p] = src[e];
}

// ---------------- attention coefficients ----------------
__global__ void att_k(const float* __restrict__ h,
                      const float* __restrict__ att_s, const float* __restrict__ att_d,
                      float* __restrict__ as_, float* __restrict__ ad_)
{
    int gw   = (blockIdx.x*blockDim.x + threadIdx.x) >> 5;
    int lane = threadIdx.x & 31;
    if (gw >= NN*NH) return;
    int n = gw >> 2, hh = gw & 3;
    const float* hp = h + (size_t)n*HF + hh*FC;
    const float* sp = att_s + hh*FC;
    const float* dp = att_d + hh*FC;
    float s = 0.f, d = 0.f;
    #pragma unroll 4
    for (int c = lane; c < FC; c += 32) {
        float v = hp[c];
        s += v * sp[c];
        d += v * dp[c];
    }
    #pragma unroll
    for (int o = 16; o; o >>= 1) {
        s += __shfl_down_sync(0xffffffffu, s, o);
        d += __shfl_down_sync(0xffffffffu, d, o);
    }
    if (lane == 0) { as_[n*NH+hh] = s; ad_[n*NH+hh] = d; }
}

// ---------------- per-dst softmax + aggregation (+bias+relu) ----------------
__global__ void agg_k(const float* __restrict__ h,
                      const float* __restrict__ as_, const float* __restrict__ ad_,
                      const int* __restrict__ rowptr, const int* __restrict__ col,
                      const float* __restrict__ bias, float* __restrict__ xout)
{
    __shared__ int   src_s[MAXE];
    __shared__ float e_s[MAXE*NH];
    __shared__ float stat[12];
    __shared__ float ad_sh[4];

    int d   = blockIdx.x;
    int tid = threadIdx.x;
    int r0  = rowptr[d];
    int deg = rowptr[d+1] - r0;
    if (deg > MAXE) deg = MAXE;

    if (tid < 4) ad_sh[tid] = ad_[d*NH + tid];
    __syncthreads();

    for (int j = tid; j < deg; j += 256) {
        int s = col[r0 + j];
        src_s[j] = s;
        #pragma unroll
        for (int hh = 0; hh < NH; hh++) {
            float e = as_[s*NH + hh] + ad_sh[hh];
            e = (e > 0.f) ? e : NEG_SLOPE * e;
            e_s[j*NH + hh] = e;
        }
    }
    __syncthreads();

    if (tid < 4) {
        int hh = tid;
        float eself = as_[d*NH + hh] + ad_sh[hh];
        eself = (eself > 0.f) ? eself : NEG_SLOPE * eself;
        float m = eself;
        for (int j = 0; j < deg; j++) m = fmaxf(m, e_s[j*NH + hh]);
        float s = __expf(eself - m);
        for (int j = 0; j < deg; j++) s += __expf(e_s[j*NH + hh] - m);
        float inv = 1.f / (s + 1e-16f);
        stat[hh]     = m;
        stat[4 + hh] = inv;
        stat[8 + hh] = __expf(eself - m) * inv;
    }
    __syncthreads();

    for (int j = tid; j < deg; j += 256) {
        #pragma unroll
        for (int hh = 0; hh < NH; hh++)
            e_s[j*NH + hh] = __expf(e_s[j*NH + hh] - stat[hh]) * stat[4 + hh];
    }
    __syncthreads();

    int c4 = tid * 4;
    int hh = c4 >> 8;
    float4 acc;
    {
        float4 v = *(const float4*)(h + (size_t)d*HF + c4);
        float a = stat[8 + hh];
        acc.x = a*v.x; acc.y = a*v.y; acc.z = a*v.z; acc.w = a*v.w;
    }
    #pragma unroll 4
    for (int j = 0; j < deg; j++) {
        float a = e_s[j*NH + hh];
        float4 v = *(const float4*)(h + (size_t)src_s[j]*HF + c4);
        acc.x += a*v.x; acc.y += a*v.y; acc.z += a*v.z; acc.w += a*v.w;
    }
    float4 bv = *(const float4*)(bias + c4);
    acc.x = fmaxf(acc.x + bv.x, 0.f);
    acc.y = fmaxf(acc.y + bv.y, 0.f);
    acc.z = fmaxf(acc.z + bv.z, 0.f);
    acc.w = fmaxf(acc.w + bv.w, 0.f);
    *(float4*)(xout + (size_t)d*HF + c4) = acc;
}

// ---------------- small fp32 tiled GEMM (only for M=64 preamble GEMMs) ----------------
__global__ void sgemm_k(const float* __restrict__ A, const float* __restrict__ B,
                        const float* __restrict__ bias, float* __restrict__ C,
                        int M, int Nc, int K, int doRelu)
{
    __shared__ float As[8][128];
    __shared__ float Bs[8][128];
    const int tid = threadIdx.x;
    const int bx = blockIdx.x, by = blockIdx.y;

    const int a_row = tid >> 1;
    const int a_k   = (tid & 1) << 2;
    const int b_k   = tid >> 5;
    const int b_col = (tid & 31) << 2;

    const int ty = tid >> 4;
    const int tx = tid & 15;
    const int row0 = by*128 + ty*8;
    const int col0 = bx*128 + tx*8;

    float acc[8][8];
    #pragma unroll
    for (int i = 0; i < 8; i++)
        #pragma unroll
        for (int j = 0; j < 8; j++) acc[i][j] = 0.f;

    const int arow_g = by*128 + a_row;
    for (int k0 = 0; k0 < K; k0 += 8) {
        float4 av = make_float4(0.f,0.f,0.f,0.f);
        if (arow_g < M)
            av = *(const float4*)(A + (size_t)arow_g*K + k0 + a_k);
        As[a_k+0][a_row] = av.x;
        As[a_k+1][a_row] = av.y;
        As[a_k+2][a_row] = av.z;
        As[a_k+3][a_row] = av.w;
        float4 bv = *(const float4*)(B + (size_t)(k0 + b_k)*Nc + bx*128 + b_col);
        *(float4*)&Bs[b_k][b_col] = bv;
        __syncthreads();

        #pragma unroll
        for (int k = 0; k < 8; k++) {
            float ar[8], br[8];
            *(float4*)&ar[0] = *(const float4*)&As[k][ty*8];
            *(float4*)&ar[4] = *(const float4*)&As[k][ty*8+4];
            *(float4*)&br[0] = *(const float4*)&Bs[k][tx*8];
            *(float4*)&br[4] = *(const float4*)&Bs[k][tx*8+4];
            #pragma unroll
            for (int i = 0; i < 8; i++)
                #pragma unroll
                for (int j = 0; j < 8; j++)
                    acc[i][j] += ar[i] * br[j];
        }
        __syncthreads();
    }

    #pragma unroll
    for (int i = 0; i < 8; i++) {
        int r = row0 + i;
        if (r >= M) break;
        #pragma unroll
        for (int j = 0; j < 8; j += 4) {
            float4 v = make_float4(acc[i][j], acc[i][j+1], acc[i][j+2], acc[i][j+3]);
            if (bias) {
                v.x += bias[col0+j+0]; v.y += bias[col0+j+1];
                v.z += bias[col0+j+2]; v.w += bias[col0+j+3];
            }
            if (doRelu) {
                v.x = fmaxf(v.x, 0.f); v.y = fmaxf(v.y, 0.f);
                v.z = fmaxf(v.z, 0.f); v.w = fmaxf(v.w, 0.f);
            }
            *(float4*)(C + (size_t)r*Nc + col0 + j) = v;
        }
    }
}

// ---------------- tiny head projection ----------------
__global__ void head2_k(const float* __restrict__ t, const float* __restrict__ Wf,
                        const float* __restrict__ bf, float* __restrict__ out, int od)
{
    int warp = (blockIdx.x*blockDim.x + threadIdx.x) >> 5;
    int lane = threadIdx.x & 31;
    if (warp >= NN) return;
    const float* tp = t + (size_t)warp*FC;
    float a0 = 0.f, a1 = 0.f;
    #pragma unroll 4
    for (int c = lane; c < FC; c += 32) {
        float v = tp[c];
        a0 += v * Wf[c*od + 0];
        if (od > 1) a1 += v * Wf[c*od + 1];
    }
    #pragma unroll
    for (int o = 16; o; o >>= 1) {
        a0 += __shfl_down_sync(0xffffffffu, a0, o);
        a1 += __shfl_down_sync(0xffffffffu, a1, o);
    }
    if (lane == 0) {
        out[(size_t)warp*od + 0] = a0 + bf[0];
        if (od > 1) out[(size_t)warp*od + 1] = a1 + bf[1];
    }
}

// ---------------- launch ----------------
extern "C" void kernel_launch(void* const* d_in, const int* in_sizes, int n_in,
                              void* d_out, int out_size)
{
    const float* z      = (const float*)d_in[0];
    const float* cond   = (const float*)d_in[1];
    const int*   ei     = (const int*)  d_in[2];
    const float* W_init = (const float*)d_in[4];
    const float* b_init = (const float*)d_in[5];
    const float* W1  = (const float*)d_in[6];
    const float* as1 = (const float*)d_in[7];
    const float* ad1 = (const float*)d_in[8];
    const float* b1  = (const float*)d_in[9];
    const float* W2  = (const float*)d_in[10];
    const float* as2 = (const float*)d_in[11];
    const float* ad2 = (const float*)d_in[12];
    const float* b2  = (const float*)d_in[13];
    const float* W3  = (const float*)d_in[14];
    const float* as3 = (const float*)d_in[15];
    const float* ad3 = (const float*)d_in[16];
    const float* b3  = (const float*)d_in[17];
    const float* Wp  = (const float*)d_in[18];
    const float* bp  = (const float*)d_in[19];
    const float* Wfp = (const float*)d_in[20];
    const float* bfp = (const float*)d_in[21];
    const float* Ws  = (const float*)d_in[22];
    const float* bs  = (const float*)d_in[23];
    const float* Wfs = (const float*)d_in[24];
    const float* bfs = (const float*)d_in[25];
    const float* Wt  = (const float*)d_in[26];
    const float* bt  = (const float*)d_in[27];
    const float* Wft = (const float*)d_in[28];
    const float* bft = (const float*)d_in[29];
    float* out = (float*)d_out;

    const int* esrc = ei;
    const int* edst = ei + NE;

    float *pxin, *pzc, *pY, *ph, *px, *pas, *pad, *pt;
    int *pcnt, *prow, *pwp, *pcol;
    cudaGetSymbolAddress((void**)&pxin, g_xin);
    cudaGetSymbolAddress((void**)&pzc,  g_zc);
    cudaGetSymbolAddress((void**)&pY,   g_Y);
    cudaGetSymbolAddress((void**)&ph,   g_h);
    cudaGetSymbolAddress((void**)&px,   g_x);
    cudaGetSymbolAddress((void**)&pas,  g_as);
    cudaGetSymbolAddress((void**)&pad,  g_ad);
    cudaGetSymbolAddress((void**)&pt,   g_t);
    cudaGetSymbolAddress((void**)&pcnt, g_cnt);
    cudaGetSymbolAddress((void**)&prow, g_rowptr);
    cudaGetSymbolAddress((void**)&pwp,  g_wp);
    cudaGetSymbolAddress((void**)&pcol, g_col);

    cudaFuncSetAttribute(mgemm_k, cudaFuncAttributeMaxDynamicSharedMemorySize, SMEM_MG);

    // 1) input projection (small, SIMT fp32)
    concat_k<<<(NB*KIN + 255)/256, 256>>>(z, cond, pxin);
    {
        dim3 g(LAT/128, 1);
        sgemm_k<<<g, 256>>>(pxin, W_init, b_init, pzc, NB, LAT, KIN, 1);
    }
    {
        dim3 g(HF/128, 1);
        sgemm_k<<<g, 256>>>(pzc, W1, nullptr, pY, NB, HF, LAT, 0);
    }
    // 2) CSR by destination
    zero_cnt_k<<<(NN + 255)/256, 256>>>(pcnt);
    count_k<<<(NE + 255)/256, 256>>>(edst, pcnt);
    scan_k<<<1, 256>>>(pcnt, prow, pwp);
    scatter_k<<<(NE + 255)/256, 256>>>(esrc, edst, pwp, pcol);

    // 3) h1 = Y[batch] + W1[256+order]  (one-hot trick: layer-1 GEMM eliminated)
    build_h1_k<<<(NN*(HF/4) + 255)/256, 256>>>(pY, W1, ph);

    // 4) layer 1: att + agg
    att_k<<<(NN*NH*32 + 255)/256, 256>>>(ph, as1, ad1, pas, pad);
    agg_k<<<NN, 256>>>(ph, pas, pad, prow, pcol, b1, px);

    // 5) layer 2: h = x @ W2 (3xTF32 mma), att + agg
    mgemm_k<<<dim3(HF/128, NN/128), 256, SMEM_MG>>>(px, W2, ph, HF, nullptr, 0);
    att_k<<<(NN*NH*32 + 255)/256, 256>>>(ph, as2, ad2, pas, pad);
    agg_k<<<NN, 256>>>(ph, pas, pad, prow, pcol, b2, px);

    // 6) layer 3
    mgemm_k<<<dim3(HF/128, NN/128), 256, SMEM_MG>>>(px, W3, ph, HF, nullptr, 0);
    att_k<<<(NN*NH*32 + 255)/256, 256>>>(ph, as3, ad3, pas, pad);
    agg_k<<<NN, 256>>>(ph, pas, pad, prow, pcol, b3, px);

    // 7) heads: t = relu(x @ Wh + bh) (3xTF32 mma); out = t @ Wf + bf (warp dot)
    mgemm_k<<<dim3(FC/128, NN/128), 256, SMEM_MG>>>(px, Wp, pt, FC, bp, 1);
    head2_k<<<(NN*32 + 255)/256, 256>>>(pt, Wfp, bfp, out, 2);

    mgemm_k<<<dim3(FC/128, NN/128), 256, SMEM_MG>>>(px, Ws, pt, FC, bs, 1);
    head2_k<<<(NN*32 + 255)/256, 256>>>(pt, Wfs, bfs, out + (size_t)2*NN, 2);

    mgemm_k<<<dim3(FC/128, NN/128), 256, SMEM_MG>>>(px, Wt, pt, FC, bt, 1);
    head2_k<<<(NN*32 + 255)/256, 256>>>(pt, Wft, bft, out + (size_t)4*NN, 1);
}

// round 10
// speedup vs baseline: 1.8848x; 1.1382x over previous
#include <cuda_runtime.h>
#include <cstdint>

// ---------------- Problem constants ----------------
#define NB      64
#define NPG     180
#define NN      (NB*NPG)    // 11520
#define NE      (NN*16)     // 184320
#define NH      4
#define FC      256
#define HF      1024
#define LAT     256
#define BOT     128
#define KIN     (LAT+BOT)
#define NEG_SLOPE 0.2f
#define MAXE    96          // per-dst edge cap (Poisson(16): max deg ~38)
#define KC      32          // K chunks of 32 (K = 1024 for all mma GEMMs)
#define HCAT    768         // merged head width (3 x 256)

// ---------------- Scratch ----------------
__device__ float g_xin[NB*KIN];
__device__ float g_zc [NB*LAT];
__device__ float g_Y  [NB*HF];
__device__ float g_h  [(size_t)NN*HF];
__device__ float g_x  [(size_t)NN*HF];
__device__ float g_as [NN*NH];
__device__ float g_ad [NN*NH];
__device__ float g_t  [(size_t)NN*HCAT];
__device__ float g_Bhi[(size_t)HF*HF];   // pre-split weight (tf32 hi), 4MB
__device__ float g_Blo[(size_t)HF*HF];   // residual lo, 4MB
__device__ float g_bcat[HCAT];
__device__ int   g_cnt[NN];
__device__ int   g_rowptr[NN+1];
__device__ int   g_wp [NN];
__device__ int   g_col[NE];

// ---------------- helpers ----------------
__device__ __forceinline__ void cpa16(uint32_t dst, const float* src) {
    asm volatile("cp.async.cg.shared.global [%0], [%1], 16;" :: "r"(dst), "l"(src));
}
__device__ __forceinline__ uint32_t tf32_hi(float x) {
    uint32_t r;
    asm("cvt.rna.tf32.f32 %0, %1;" : "=r"(r) : "f"(x));
    return r;
}
#define MMA_TF32(ac, a0, a1, a2, a3, b0, b1)                                   \
    asm volatile("mma.sync.aligned.m16n8k8.row.col.f32.tf32.tf32.f32 "         \
        "{%0,%1,%2,%3}, {%4,%5,%6,%7}, {%8,%9}, {%0,%1,%2,%3};"                \
        : "+f"((ac)[0]), "+f"((ac)[1]), "+f"((ac)[2]), "+f"((ac)[3])           \
        : "r"(a0), "r"(a1), "r"(a2), "r"(a3), "r"(b0), "r"(b1))

// ---------------- weight pre-split kernels ----------------
__global__ void wsplit_k(const float* __restrict__ W, float* __restrict__ hi,
                         float* __restrict__ lo, int n)
{
    int idx = blockIdx.x*blockDim.x + threadIdx.x;
    if (idx >= n) return;
    float v = W[idx];
    float h = __uint_as_float(tf32_hi(v));
    hi[idx] = h;
    lo[idx] = v - h;
}

// concat Wp|Ws|Wt ([1024,256] each) -> split [1024,768]; also concat biases
__global__ void hcat_k(const float* __restrict__ Wp, const float* __restrict__ Ws,
                       const float* __restrict__ Wt,
                       const float* __restrict__ bp, const float* __restrict__ bs,
                       const float* __restrict__ bt,
                       float* __restrict__ hi, float* __restrict__ lo,
                       float* __restrict__ bcat)
{
    int idx = blockIdx.x*blockDim.x + threadIdx.x;
    if (idx >= HF*HCAT) return;
    int k = idx / HCAT, c = idx % HCAT;
    const float* W = (c < 256) ? Wp : ((c < 512) ? Ws : Wt);
    int cc = c & 255;
    float v = W[(size_t)k*FC + cc];
    float h = __uint_as_float(tf32_hi(v));
    hi[idx] = h;
    lo[idx] = v - h;
    if (idx < HCAT)
        bcat[idx] = (idx < 256) ? bp[idx] : ((idx < 512) ? bs[idx-256] : bt[idx-512]);
}

// ---------------- 3xTF32 mma.sync GEMM (pre-split B) ----------------
// C[M,Nc] = A[M,1024] @ B[1024,Nc] (+bias)(+relu).  M%128==0, Nc%128==0.
// CTA tile 128x128, BK=32, 256 threads = 8 warps (4M x 2N), warp tile 32x64.
// A split hi/lo in-loop; B pre-split in global (Bhi/Blo).
#define PA 36
#define PB 136               // (136%32)=8 -> b-frag bank = 8*tig+g, conflict-free
#define ASTG (128*PA)        // 4608 floats
#define BSTG (32*PB)         // 4352 floats (per hi or lo buffer)
#define STG  (ASTG + 2*BSTG) // 13312 floats = 53248 B
#define SMEM_MG (2*STG*4)    // 106496 B

__global__ void __launch_bounds__(256, 2) mgemm_k(
    const float* __restrict__ A, const float* __restrict__ Bhi,
    const float* __restrict__ Blo, float* __restrict__ C,
    int Nc, const float* __restrict__ bias, int doRelu)
{
    extern __shared__ float sm[];
    const int tid  = threadIdx.x;
    const int wid  = tid >> 5, lane = tid & 31;
    const int wm   = wid >> 1, wn   = wid & 1;
    const int g    = lane >> 2, tig = lane & 3;
    const int m0   = blockIdx.y * 128;
    const int n0   = blockIdx.x * 128;

    float acc[2][8][4];
    #pragma unroll
    for (int mt = 0; mt < 2; mt++)
        #pragma unroll
        for (int nt = 0; nt < 8; nt++)
            #pragma unroll
            for (int i = 0; i < 4; i++) acc[mt][nt][i] = 0.f;

    auto loadst = [&](int c, int s) {
        float* Asm = sm + s*STG;
        float* Bh  = Asm + ASTG;
        float* Bl  = Bh + BSTG;
        const int k0 = c << 5;
        #pragma unroll
        for (int j = 0; j < 4; j++) {
            int idx = tid + j*256;
            int row = idx >> 3, cf = (idx & 7) << 2;
            uint32_t dst = (uint32_t)__cvta_generic_to_shared(Asm + row*PA + cf);
            cpa16(dst, A + (size_t)(m0 + row)*HF + k0 + cf);
        }
        #pragma unroll
        for (int j = 0; j < 4; j++) {
            int idx = tid + j*256;
            int row = idx >> 5, cf = (idx & 31) << 2;
            size_t goff = (size_t)(k0 + row)*Nc + n0 + cf;
            uint32_t d1 = (uint32_t)__cvta_generic_to_shared(Bh + row*PB + cf);
            cpa16(d1, Bhi + goff);
            uint32_t d2 = (uint32_t)__cvta_generic_to_shared(Bl + row*PB + cf);
            cpa16(d2, Blo + goff);
        }
        asm volatile("cp.async.commit_group;" ::: "memory");
    };

    auto compute = [&](int s) {
        const float* Asm = sm + s*STG;
        const float* Bh  = Asm + ASTG;
        const float* Bl  = Bh + BSTG;
        const float* ab  = Asm + (wm*32 + g)*PA + tig;
        const int    bo  = tig*PB + wn*64 + g;
        #pragma unroll
        for (int ks = 0; ks < 4; ks++) {
            uint32_t ah[2][4], al[2][4];
            #pragma unroll
            for (int mt = 0; mt < 2; mt++) {
                const float* p = ab + mt*16*PA + ks*8;
                float f0 = p[0], f1 = p[8*PA], f2 = p[4], f3 = p[8*PA + 4];
                ah[mt][0] = tf32_hi(f0); al[mt][0] = __float_as_uint(f0 - __uint_as_float(ah[mt][0]));
                ah[mt][1] = tf32_hi(f1); al[mt][1] = __float_as_uint(f1 - __uint_as_float(ah[mt][1]));
                ah[mt][2] = tf32_hi(f2); al[mt][2] = __float_as_uint(f2 - __uint_as_float(ah[mt][2]));
                ah[mt][3] = tf32_hi(f3); al[mt][3] = __float_as_uint(f3 - __uint_as_float(ah[mt][3]));
            }
            #pragma unroll
            for (int ntg = 0; ntg < 2; ntg++) {
                uint32_t bh[4][2], bl[4][2];
                #pragma unroll
                for (int q = 0; q < 4; q++) {
                    int off = bo + ks*8*PB + (ntg*4 + q)*8;
                    bh[q][0] = __float_as_uint(Bh[off]);
                    bh[q][1] = __float_as_uint(Bh[off + 4*PB]);
                    bl[q][0] = __float_as_uint(Bl[off]);
                    bl[q][1] = __float_as_uint(Bl[off + 4*PB]);
                }
                #pragma unroll
                for (int mt = 0; mt < 2; mt++)
                    #pragma unroll
                    for (int q = 0; q < 4; q++) {
                        float* ac = acc[mt][ntg*4 + q];
                        MMA_TF32(ac, ah[mt][0], ah[mt][1], ah[mt][2], ah[mt][3], bh[q][0], bh[q][1]);
                        MMA_TF32(ac, ah[mt][0], ah[mt][1], ah[mt][2], ah[mt][3], bl[q][0], bl[q][1]);
                        MMA_TF32(ac, al[mt][0], al[mt][1], al[mt][2], al[mt][3], bh[q][0], bh[q][1]);
                    }
            }
        }
    };

    loadst(0, 0);
    loadst(1, 1);
    for (int c = 0; c < KC; c++) {
        int s = c & 1;
        if (c < KC - 2) asm volatile("cp.async.wait_group 1;" ::: "memory");
        else            asm volatile("cp.async.wait_group 0;" ::: "memory");
        __syncthreads();
        compute(s);
        __syncthreads();
        if (c + 2 < KC) loadst(c + 2, s);
    }

    // epilogue
    #pragma unroll
    for (int mt = 0; mt < 2; mt++) {
        int r = m0 + wm*32 + mt*16 + g;
        #pragma unroll
        for (int nt = 0; nt < 8; nt++) {
            int col = n0 + wn*64 + nt*8 + 2*tig;
            float2 v0 = make_float2(acc[mt][nt][0], acc[mt][nt][1]);
            float2 v1 = make_float2(acc[mt][nt][2], acc[mt][nt][3]);
            if (bias) {
                float2 bv = *(const float2*)(bias + col);
                v0.x += bv.x; v0.y += bv.y;
                v1.x += bv.x; v1.y += bv.y;
            }
            if (doRelu) {
                v0.x = fmaxf(v0.x, 0.f); v0.y = fmaxf(v0.y, 0.f);
                v1.x = fmaxf(v1.x, 0.f); v1.y = fmaxf(v1.y, 0.f);
            }
            *(float2*)(C + (size_t)r*Nc + col)       = v0;
            *(float2*)(C + (size_t)(r + 8)*Nc + col) = v1;
        }
    }
}

// ---------------- small utility kernels ----------------
__global__ void concat_k(const float* __restrict__ z, const float* __restrict__ c,
                         float* __restrict__ out)
{
    int idx = blockIdx.x*blockDim.x + threadIdx.x;
    if (idx >= NB*KIN) return;
    int b = idx / KIN, i = idx % KIN;
    out[idx] = (i < LAT) ? z[b*LAT + i] : c[b*BOT + (i-LAT)];
}

__global__ void build_h1_k(const float* __restrict__ Y, const float* __restrict__ W1,
                           float* __restrict__ h)
{
    int idx = blockIdx.x*blockDim.x + threadIdx.x;
    if (idx >= NN*(HF/4)) return;
    int n  = idx >> 8;
    int c4 = (idx & 255) << 2;
    int b = n / NPG, o = n % NPG;
    float4 yv = *(const float4*)(Y + (size_t)b*HF + c4);
    float4 wv = *(const float4*)(W1 + (size_t)(LAT + o)*HF + c4);
    yv.x += wv.x; yv.y += wv.y; yv.z += wv.z; yv.w += wv.w;
    *(float4*)(h + (size_t)n*HF + c4) = yv;
}

__global__ void zero_cnt_k(int* __restrict__ cnt)
{
    int i = blockIdx.x*blockDim.x + threadIdx.x;
    if (i < NN) cnt[i] = 0;
}

__global__ void count_k(const int* __restrict__ dst, int* __restrict__ cnt)
{
    int e = blockIdx.x*blockDim.x + threadIdx.x;
    if (e < NE) atomicAdd(&cnt[dst[e]], 1);
}

__global__ void scan_k(const int* __restrict__ cnt, int* __restrict__ rowptr,
                       int* __restrict__ wp)
{
    __shared__ int sums[256];
    const int CH = (NN + 255) / 256;
    int t = threadIdx.x;
    int base = t * CH;
    int s = 0;
    for (int i = 0; i < CH; i++) { int idx = base + i; if (idx < NN) s += cnt[idx]; }
    sums[t] = s;
    __syncthreads();
    if (t == 0) {
        int run = 0;
        for (int i = 0; i < 256; i++) { int v = sums[i]; sums[i] = run; run += v; }
        rowptr[NN] = run;
    }
    __syncthreads();
    int run = sums[t];
    for (int i = 0; i < CH; i++) {
        int idx = base + i;
        if (idx < NN) { rowptr[idx] = run; wp[idx] = run; run += cnt[idx]; }
    }
}

__global__ void scatter_k(const int* __restrict__ src, const int* __restrict__ dst,
                          int* __restrict__ wp, int* __restrict__ col)
{
    int e = blockIdx.x*blockDim.x + threadIdx.x;
    if (e >= NE) return;
    int d = dst[e];
    int p = atomicAdd(&wp[d], 1);
    col[p] = src[e];
}

// ---------------- attention coefficients ----------------
__global__ void att_k(const float* __restrict__ h,
                      const float* __restrict__ att_s, const float* __restrict__ att_d,
                      float* __restrict__ as_, float* __restrict__ ad_)
{
    int gw   = (blockIdx.x*blockDim.x + threadIdx.x) >> 5;
    int lane = threadIdx.x & 31;
    if (gw >= NN*NH) return;
    int n = gw >> 2, hh = gw & 3;
    const float* hp = h + (size_t)n*HF + hh*FC;
    const float* sp = att_s + hh*FC;
    const float* dp = att_d + hh*FC;
    float s = 0.f, d = 0.f;
    #pragma unroll 4
    for (int c = lane; c < FC; c += 32) {
        float v = hp[c];
        s += v * sp[c];
        d += v * dp[c];
    }
    #pragma unroll
    for (int o = 16; o; o >>= 1) {
        s += __shfl_down_sync(0xffffffffu, s, o);
        d += __shfl_down_sync(0xffffffffu, d, o);
    }
    if (lane == 0) { as_[n*NH+hh] = s; ad_[n*NH+hh] = d; }
}

// ---------------- per-dst softmax + aggregation (+bias+relu) ----------------
__global__ void agg_k(const float* __restrict__ h,
                      const float* __restrict__ as_, const float* __restrict__ ad_,
                      const int* __restrict__ rowptr, const int* __restrict__ col,
                      const float* __restrict__ bias, float* __restrict__ xout)
{
    __shared__ int   src_s[MAXE];
    __shared__ float e_s[MAXE*NH];
    __shared__ float stat[12];
    __shared__ float ad_sh[4];

    int d   = blockIdx.x;
    int tid = threadIdx.x;
    int r0  = rowptr[d];
    int deg = rowptr[d+1] - r0;
    if (deg > MAXE) deg = MAXE;

    if (tid < 4) ad_sh[tid] = ad_[d*NH + tid];
    __syncthreads();

    for (int j = tid; j < deg; j += 256) {
        int s = col[r0 + j];
        src_s[j] = s;
        #pragma unroll
        for (int hh = 0; hh < NH; hh++) {
            float e = as_[s*NH + hh] + ad_sh[hh];
            e = (e > 0.f) ? e : NEG_SLOPE * e;
            e_s[j*NH + hh] = e;
        }
    }
    __syncthreads();

    if (tid < 4) {
        int hh = tid;
        float eself = as_[d*NH + hh] + ad_sh[hh];
        eself = (eself > 0.f) ? eself : NEG_SLOPE * eself;
        float m = eself;
        for (int j = 0; j < deg; j++) m = fmaxf(m, e_s[j*NH + hh]);
        float s = __expf(eself - m);
        for (int j = 0; j < deg; j++) s += __expf(e_s[j*NH + hh] - m);
        float inv = 1.f / (s + 1e-16f);
        stat[hh]     = m;
        stat[4 + hh] = inv;
        stat[8 + hh] = __expf(eself - m) * inv;
    }
    __syncthreads();

    for (int j = tid; j < deg; j += 256) {
        #pragma unroll
        for (int hh = 0; hh < NH; hh++)
            e_s[j*NH + hh] = __expf(e_s[j*NH + hh] - stat[hh]) * stat[4 + hh];
    }
    __syncthreads();

    int c4 = tid * 4;
    int hh = c4 >> 8;
    float4 acc;
    {
        float4 v = *(const float4*)(h + (size_t)d*HF + c4);
        float a = stat[8 + hh];
        acc.x = a*v.x; acc.y = a*v.y; acc.z = a*v.z; acc.w = a*v.w;
    }
    #pragma unroll 4
    for (int j = 0; j < deg; j++) {
        float a = e_s[j*NH + hh];
        float4 v = *(const float4*)(h + (size_t)src_s[j]*HF + c4);
        acc.x += a*v.x; acc.y += a*v.y; acc.z += a*v.z; acc.w += a*v.w;
    }
    float4 bv = *(const float4*)(bias + c4);
    acc.x = fmaxf(acc.x + bv.x, 0.f);
    acc.y = fmaxf(acc.y + bv.y, 0.f);
    acc.z = fmaxf(acc.z + bv.z, 0.f);
    acc.w = fmaxf(acc.w + bv.w, 0.f);
    *(float4*)(xout + (size_t)d*HF + c4) = acc;
}

// ---------------- small fp32 tiled GEMM (only for M=64 preamble GEMMs) ----------------
__global__ void sgemm_k(const float* __restrict__ A, const float* __restrict__ B,
                        const float* __restrict__ bias, float* __restrict__ C,
                        int M, int Nc, int K, int doRelu)
{
    __shared__ float As[8][128];
    __shared__ float Bs[8][128];
    const int tid = threadIdx.x;
    const int bx = blockIdx.x, by = blockIdx.y;

    const int a_row = tid >> 1;
    const int a_k   = (tid & 1) << 2;
    const int b_k   = tid >> 5;
    const int b_col = (tid & 31) << 2;

    const int ty = tid >> 4;
    const int tx = tid & 15;
    const int row0 = by*128 + ty*8;
    const int col0 = bx*128 + tx*8;

    float acc[8][8];
    #pragma unroll
    for (int i = 0; i < 8; i++)
        #pragma unroll
        for (int j = 0; j < 8; j++) acc[i][j] = 0.f;

    const int arow_g = by*128 + a_row;
    for (int k0 = 0; k0 < K; k0 += 8) {
        float4 av = make_float4(0.f,0.f,0.f,0.f);
        if (arow_g < M)
            av = *(const float4*)(A + (size_t)arow_g*K + k0 + a_k);
        As[a_k+0][a_row] = av.x;
        As[a_k+1][a_row] = av.y;
        As[a_k+2][a_row] = av.z;
        As[a_k+3][a_row] = av.w;
        float4 bv = *(const float4*)(B + (size_t)(k0 + b_k)*Nc + bx*128 + b_col);
        *(float4*)&Bs[b_k][b_col] = bv;
        __syncthreads();

        #pragma unroll
        for (int k = 0; k < 8; k++) {
            float ar[8], br[8];
            *(float4*)&ar[0] = *(const float4*)&As[k][ty*8];
            *(float4*)&ar[4] = *(const float4*)&As[k][ty*8+4];
            *(float4*)&br[0] = *(const float4*)&Bs[k][tx*8];
            *(float4*)&br[4] = *(const float4*)&Bs[k][tx*8+4];
            #pragma unroll
            for (int i = 0; i < 8; i++)
                #pragma unroll
                for (int j = 0; j < 8; j++)
                    acc[i][j] += ar[i] * br[j];
        }
        __syncthreads();
    }

    #pragma unroll
    for (int i = 0; i < 8; i++) {
        int r = row0 + i;
        if (r >= M) break;
        #pragma unroll
        for (int j = 0; j < 8; j += 4) {
            float4 v = make_float4(acc[i][j], acc[i][j+1], acc[i][j+2], acc[i][j+3]);
            if (bias) {
                v.x += bias[col0+j+0]; v.y += bias[col0+j+1];
                v.z += bias[col0+j+2]; v.w += bias[col0+j+3];
            }
            if (doRelu) {
                v.x = fmaxf(v.x, 0.f); v.y = fmaxf(v.y, 0.f);
                v.z = fmaxf(v.z, 0.f); v.w = fmaxf(v.w, 0.f);
            }
            *(float4*)(C + (size_t)r*Nc + col0 + j) = v;
        }
    }
}

// ---------------- tiny head projection (t has row stride HCAT) ----------------
__global__ void head2_k(const float* __restrict__ t, const float* __restrict__ Wf,
                        const float* __restrict__ bf, float* __restrict__ out, int od)
{
    int warp = (blockIdx.x*blockDim.x + threadIdx.x) >> 5;
    int lane = threadIdx.x & 31;
    if (warp >= NN) return;
    const float* tp = t + (size_t)warp*HCAT;
    float a0 = 0.f, a1 = 0.f;
    #pragma unroll 4
    for (int c = lane; c < FC; c += 32) {
        float v = tp[c];
        a0 += v * Wf[c*od + 0];
        if (od > 1) a1 += v * Wf[c*od + 1];
    }
    #pragma unroll
    for (int o = 16; o; o >>= 1) {
        a0 += __shfl_down_sync(0xffffffffu, a0, o);
        a1 += __shfl_down_sync(0xffffffffu, a1, o);
    }
    if (lane == 0) {
        out[(size_t)warp*od + 0] = a0 + bf[0];
        if (od > 1) out[(size_t)warp*od + 1] = a1 + bf[1];
    }
}

// ---------------- launch ----------------
extern "C" void kernel_launch(void* const* d_in, const int* in_sizes, int n_in,
                              void* d_out, int out_size)
{
    const float* z      = (const float*)d_in[0];
    const float* cond   = (const float*)d_in[1];
    const int*   ei     = (const int*)  d_in[2];
    const float* W_init = (const float*)d_in[4];
    const float* b_init = (const float*)d_in[5];
    const float* W1  = (const float*)d_in[6];
    const float* as1 = (const float*)d_in[7];
    const float* ad1 = (const float*)d_in[8];
    const float* b1  = (const float*)d_in[9];
    const float* W2  = (const float*)d_in[10];
    const float* as2 = (const float*)d_in[11];
    const float* ad2 = (const float*)d_in[12];
    const float* b2  = (const float*)d_in[13];
    const float* W3  = (const float*)d_in[14];
    const float* as3 = (const float*)d_in[15];
    const float* ad3 = (const float*)d_in[16];
    const float* b3  = (const float*)d_in[17];
    const float* Wp  = (const float*)d_in[18];
    const float* bp  = (const float*)d_in[19];
    const float* Wfp = (const float*)d_in[20];
    const float* bfp = (const float*)d_in[21];
    const float* Ws  = (const float*)d_in[22];
    const float* bs  = (const float*)d_in[23];
    const float* Wfs = (const float*)d_in[24];
    const float* bfs = (const float*)d_in[25];
    const float* Wt  = (const float*)d_in[26];
    const float* bt  = (const float*)d_in[27];
    const float* Wft = (const float*)d_in[28];
    const float* bft = (const float*)d_in[29];
    float* out = (float*)d_out;

    const int* esrc = ei;
    const int* edst = ei + NE;

    float *pxin, *pzc, *pY, *ph, *px, *pas, *pad, *pt, *phi, *plo, *pbc;
    int *pcnt, *prow, *pwp, *pcol;
    cudaGetSymbolAddress((void**)&pxin, g_xin);
    cudaGetSymbolAddress((void**)&pzc,  g_zc);
    cudaGetSymbolAddress((void**)&pY,   g_Y);
    cudaGetSymbolAddress((void**)&ph,   g_h);
    cudaGetSymbolAddress((void**)&px,   g_x);
    cudaGetSymbolAddress((void**)&pas,  g_as);
    cudaGetSymbolAddress((void**)&pad,  g_ad);
    cudaGetSymbolAddress((void**)&pt,   g_t);
    cudaGetSymbolAddress((void**)&phi,  g_Bhi);
    cudaGetSymbolAddress((void**)&plo,  g_Blo);
    cudaGetSymbolAddress((void**)&pbc,  g_bcat);
    cudaGetSymbolAddress((void**)&pcnt, g_cnt);
    cudaGetSymbolAddress((void**)&prow, g_rowptr);
    cudaGetSymbolAddress((void**)&pwp,  g_wp);
    cudaGetSymbolAddress((void**)&pcol, g_col);

    cudaFuncSetAttribute(mgemm_k, cudaFuncAttributeMaxDynamicSharedMemorySize, SMEM_MG);

    // 1) input projection (small, SIMT fp32)
    concat_k<<<(NB*KIN + 255)/256, 256>>>(z, cond, pxin);
    {
        dim3 g(LAT/128, 1);
        sgemm_k<<<g, 256>>>(pxin, W_init, b_init, pzc, NB, LAT, KIN, 1);
    }
    {
        dim3 g(HF/128, 1);
        sgemm_k<<<g, 256>>>(pzc, W1, nullptr, pY, NB, HF, LAT, 0);
    }
    // 2) CSR by destination
    zero_cnt_k<<<(NN + 255)/256, 256>>>(pcnt);
    count_k<<<(NE + 255)/256, 256>>>(edst, pcnt);
    scan_k<<<1, 256>>>(pcnt, prow, pwp);
    scatter_k<<<(NE + 255)/256, 256>>>(esrc, edst, pwp, pcol);

    // 3) h1 = Y[batch] + W1[256+order]  (one-hot trick: layer-1 GEMM eliminated)
    build_h1_k<<<(NN*(HF/4) + 255)/256, 256>>>(pY, W1, ph);

    // 4) layer 1: att + agg
    att_k<<<(NN*NH*32 + 255)/256, 256>>>(ph, as1, ad1, pas, pad);
    agg_k<<<NN, 256>>>(ph, pas, pad, prow, pcol, b1, px);

    // 5) layer 2: split W2, h = x @ W2 (3xTF32), att + agg
    wsplit_k<<<(HF*HF + 255)/256, 256>>>(W2, phi, plo, HF*HF);
    mgemm_k<<<dim3(HF/128, NN/128), 256, SMEM_MG>>>(px, phi, plo, ph, HF, nullptr, 0);
    att_k<<<(NN*NH*32 + 255)/256, 256>>>(ph, as2, ad2, pas, pad);
    agg_k<<<NN, 256>>>(ph, pas, pad, prow, pcol, b2, px);

    // 6) layer 3
    wsplit_k<<<(HF*HF + 255)/256, 256>>>(W3, phi, plo, HF*HF);
    mgemm_k<<<dim3(HF/128, NN/128), 256, SMEM_MG>>>(px, phi, plo, ph, HF, nullptr, 0);
    att_k<<<(NN*NH*32 + 255)/256, 256>>>(ph, as3, ad3, pas, pad);
    agg_k<<<NN, 256>>>(ph, pas, pad, prow, pcol, b3, px);

    // 7) heads: merged t = relu(x @ [Wp|Ws|Wt] + bcat) in ONE Nc=768 GEMM
    hcat_k<<<(HF*HCAT + 255)/256, 256>>>(Wp, Ws, Wt, bp, bs, bt, phi, plo, pbc);
    mgemm_k<<<dim3(HCAT/128, NN/128), 256, SMEM_MG>>>(px, phi, plo, pt, HCAT, pbc, 1);

    head2_k<<<(NN*32 + 255)/256, 256>>>(pt,       Wfp, bfp, out, 2);
    head2_k<<<(NN*32 + 255)/256, 256>>>(pt + 256, Wfs, bfs, out + (size_t)2*NN, 2);
    head2_k<<<(NN*32 + 255)/256, 256>>>(pt + 512, Wft, bft, out + (size_t)4*NN, 1);
}